// round 14
// baseline (speedup 1.0000x reference)
#include <cuda_runtime.h>
#include <cuda_bf16.h>
#include <cuda_fp16.h>

#define BB 2
#define HH 12
#define SS 2048
#define DD 64
#define BH 24
#define NROWS 49152

// Scratch: fp16 normalized Q/K and masked V
__device__ __half g_qf[(size_t)NROWS * DD];
__device__ __half g_kf[(size_t)NROWS * DD];
__device__ __half g_vf[(size_t)NROWS * DD];

// ---------------------------------------------------------------------------
// helpers
// ---------------------------------------------------------------------------
__device__ __forceinline__ unsigned smem_u32(const void* p)
{
    unsigned a;
    asm("{ .reg .u64 t; cvta.to.shared.u64 t, %1; cvt.u32.u64 %0, t; }"
        : "=r"(a) : "l"(p));
    return a;
}
__device__ __forceinline__ unsigned sw128(unsigned off)
{
    return off ^ ((off >> 3) & 0x70);
}
__device__ __forceinline__ unsigned pack_h2(float lo, float hi)
{
    unsigned r;
    asm("cvt.rn.f16x2.f32 %0, %1, %2;" : "=r"(r) : "f"(hi), "f"(lo));
    return r;
}
__device__ __forceinline__ void ldsm4(unsigned* r, unsigned addr)
{
    asm volatile("ldmatrix.sync.aligned.m8n8.x4.shared.b16 {%0,%1,%2,%3}, [%4];"
                 : "=r"(r[0]), "=r"(r[1]), "=r"(r[2]), "=r"(r[3]) : "r"(addr));
}
__device__ __forceinline__ void ldsm4t(unsigned* r, unsigned addr)
{
    asm volatile("ldmatrix.sync.aligned.m8n8.x4.trans.shared.b16 {%0,%1,%2,%3}, [%4];"
                 : "=r"(r[0]), "=r"(r[1]), "=r"(r[2]), "=r"(r[3]) : "r"(addr));
}
__device__ __forceinline__ void mma16816(float* c, const unsigned* a,
                                         const unsigned* b)
{
    asm volatile(
        "mma.sync.aligned.m16n8k16.row.col.f32.f16.f16.f32 "
        "{%0,%1,%2,%3}, {%4,%5,%6,%7}, {%8,%9}, {%0,%1,%2,%3};"
        : "+f"(c[0]), "+f"(c[1]), "+f"(c[2]), "+f"(c[3])
        : "r"(a[0]), "r"(a[1]), "r"(a[2]), "r"(a[3]), "r"(b[0]), "r"(b[1]));
}
__device__ __forceinline__ void cp16(unsigned dst, const void* src)
{
    asm volatile("cp.async.cg.shared.global [%0], [%1], 16;"
                 :: "r"(dst), "l"(src) : "memory");
}
__device__ __forceinline__ void cp_commit()
{
    asm volatile("cp.async.commit_group;" ::: "memory");
}
template <int N>
__device__ __forceinline__ void cp_wait()
{
    asm volatile("cp.async.wait_group %0;" :: "n"(N) : "memory");
}

// ---------------------------------------------------------------------------
// Prep: l2norm Q,K rows -> fp16; vm = V*mask -> fp16
// ---------------------------------------------------------------------------
__global__ void __launch_bounds__(256) yoso_prep(
    const float* __restrict__ Q, const float* __restrict__ K,
    const float* __restrict__ V, const float* __restrict__ mask)
{
    int r = blockIdx.x * 8 + threadIdx.y;
    int lane = threadIdx.x;
    int s = r % SS;
    int b = r / (HH * SS);
    float m = mask[b * SS + s];
    size_t off = (size_t)r * DD;
    size_t uoff = (size_t)r * 32 + lane;

    {
        float2 v = *(const float2*)(Q + off + lane * 2);
        float sq = v.x * v.x + v.y * v.y;
        sq += __shfl_xor_sync(0xffffffff, sq, 16);
        sq += __shfl_xor_sync(0xffffffff, sq, 8);
        sq += __shfl_xor_sync(0xffffffff, sq, 4);
        sq += __shfl_xor_sync(0xffffffff, sq, 2);
        sq += __shfl_xor_sync(0xffffffff, sq, 1);
        float inv = 1.0f / fmaxf(sqrtf(sq), 1e-12f);
        ((unsigned*)g_qf)[uoff] = pack_h2(v.x * inv, v.y * inv);
    }
    {
        float2 v = *(const float2*)(K + off + lane * 2);
        float sq = v.x * v.x + v.y * v.y;
        sq += __shfl_xor_sync(0xffffffff, sq, 16);
        sq += __shfl_xor_sync(0xffffffff, sq, 8);
        sq += __shfl_xor_sync(0xffffffff, sq, 4);
        sq += __shfl_xor_sync(0xffffffff, sq, 2);
        sq += __shfl_xor_sync(0xffffffff, sq, 1);
        float inv = 1.0f / fmaxf(sqrtf(sq), 1e-12f);
        ((unsigned*)g_kf)[uoff] = pack_h2(v.x * inv, v.y * inv);
    }
    {
        float2 v = *(const float2*)(V + off + lane * 2);
        ((unsigned*)g_vf)[uoff] = pack_h2(v.x * m, v.y * m);
    }
}

// ---------------------------------------------------------------------------
// Fast branchless W(x) = (1 - acos(x)/pi)^8
// ---------------------------------------------------------------------------
__device__ __forceinline__ float yoso_w(float x)
{
    float ax = fminf(fabsf(x), 1.0f);
    float s;
    asm("sqrt.approx.f32 %0, %1;" : "=f"(s) : "f"(1.0f - ax));
    float p = fmaf(-0.00596158f, ax, 0.02363848f);
    p = fmaf(p, ax, -0.06751817f);
    p = fmaf(p, ax, 0.49997907f);
    float u = s * p;
    float t = 0.5f + copysignf(0.5f - u, x);
    float t2 = t * t;
    float t4 = t2 * t2;
    return t4 * t4;
}

// ---------------------------------------------------------------------------
// Main kernel: single-product fp16 mma.sync, double-buffered cp.async.
// Key-half interleaving: GEMM1(h)->transform(h)->GEMM2(h) per 32-key half,
// shrinking wf/dts live ranges (5 CTAs/SM) and giving cross-phase ILP.
// smem: Q | K0 | K1 | V0 | V1   (8KB each, 40KB total)
// ---------------------------------------------------------------------------
#define SM_Q  0
#define SM_K0 8192
#define SM_K1 16384
#define SM_V0 24576
#define SM_V1 32768
#define SMEM_BYTES 40960

// async-copy one 64x64 fp16 tile (128B rows, SW128 swizzle)
__device__ __forceinline__ void cp_tile64(
    unsigned dst, const __half* g, int tid)
{
    #pragma unroll
    for (int i = 0; i < 4; ++i) {
        int c = tid + i * 128;
        int row = c >> 3;
        int col = c & 7;
        cp16(dst + sw128((unsigned)(row * 128 + col * 16)),
             g + (size_t)row * DD + col * 8);
    }
}

__global__ void __launch_bounds__(128, 5) yoso_mma(
    const float* __restrict__ mask, const float* __restrict__ convw,
    float* __restrict__ out)
{
    extern __shared__ char smc[];
    const int tid = threadIdx.x;
    const int wid = tid >> 5;
    const int lane = tid & 31;
    const int bh = blockIdx.y;
    const int h = bh % HH;
    const int b = bh / HH;
    const int row0 = blockIdx.x * 64;
    const size_t base = (size_t)bh * SS * DD;
    const unsigned smb = smem_u32(smc);

    // prologue: async-load Q, K(0), V(0)
    cp_tile64(smb + SM_Q, g_qf + base + (size_t)row0 * DD, tid);
    cp_tile64(smb + SM_K0, g_kf + base, tid);
    cp_tile64(smb + SM_V0, g_vf + base, tid);
    cp_commit();

    // ldmatrix lane offsets
    const int mm = lane >> 3;
    const int r8 = lane & 7;
    const unsigned aOff = (unsigned)((16 * wid + (mm & 1) * 8 + r8) * 128
                                     + 16 * (mm >> 1));
    const int kRow = r8 + 8 * (mm >> 1);
    const int kCol = 16 * (mm & 1);
    const int vRow = r8 + 8 * (mm & 1);
    const int vCol = 16 * (mm >> 1);

    // Q A-fragments: load ONCE, reuse across all key tiles
    cp_wait<0>();
    __syncthreads();
    unsigned aF[4][4];
    #pragma unroll
    for (int t = 0; t < 4; ++t) {
        ldsm4(aF[t], smb + SM_Q + sw128(aOff + 32 * t));
    }

    float acc[8][4];
    #pragma unroll
    for (int j = 0; j < 8; ++j) {
        #pragma unroll
        for (int i = 0; i < 4; ++i) {
            acc[j][i] = 0.0f;
        }
    }

    for (int kt = 0; kt < SS / 64; ++kt) {
        const unsigned kcur = (kt & 1) ? SM_K1 : SM_K0;
        const unsigned knxt = (kt & 1) ? SM_K0 : SM_K1;
        const unsigned vcur = (kt & 1) ? SM_V1 : SM_V0;
        const unsigned vnxt = (kt & 1) ? SM_V0 : SM_V1;

        // K(kt), V(kt) complete; barrier retires readers of buffers we
        // overwrite next.
        cp_wait<0>();
        __syncthreads();

        // issue K(kt+1), V(kt+1) into the opposite stage
        {
            const int kb2 = ((kt + 1) & 31) * 64;
            cp_tile64(smb + knxt, g_kf + base + (size_t)kb2 * DD, tid);
            cp_tile64(smb + vnxt, g_vf + base + (size_t)kb2 * DD, tid);
            cp_commit();
        }

        // ---- per 32-key half: GEMM1 -> transform -> GEMM2 ----
        #pragma unroll
        for (int hf = 0; hf < 2; ++hf) {
            // GEMM1: dots for keys [32*hf, 32*hf+32)
            float dts[4][4];
            #pragma unroll
            for (int j = 0; j < 4; ++j) {
                #pragma unroll
                for (int i = 0; i < 4; ++i) {
                    dts[j][i] = 0.0f;
                }
            }
            #pragma unroll
            for (int t = 0; t < 4; ++t) {
                #pragma unroll
                for (int uu = 0; uu < 2; ++uu) {
                    int u = 2 * hf + uu;
                    unsigned bF[4];
                    unsigned off = sw128((unsigned)((16 * u + kRow) * 128
                                                    + 32 * t + kCol));
                    ldsm4(bF, smb + kcur + off);
                    mma16816(dts[2 * uu],     aF[t], bF);
                    mma16816(dts[2 * uu + 1], aF[t], bF + 2);
                }
            }

            // transform -> fp16 A-fragments for this half (wf: 8 regs)
            unsigned wf[2][4];
            #pragma unroll
            for (int uu = 0; uu < 2; ++uu) {
                #pragma unroll
                for (int q2 = 0; q2 < 4; ++q2) {
                    int j = 2 * uu + (q2 >> 1);
                    int g = q2 & 1;
                    float f0 = yoso_w(dts[j][2 * g]);
                    float f1 = yoso_w(dts[j][2 * g + 1]);
                    wf[uu][q2] = pack_h2(f0, f1);
                }
            }

            // GEMM2: acc += W[:, keys of this half] * V[keys of this half, :]
            #pragma unroll
            for (int uu = 0; uu < 2; ++uu) {
                int t2 = 2 * hf + uu;
                #pragma unroll
                for (int u = 0; u < 4; ++u) {
                    unsigned vF[4];
                    unsigned off = sw128((unsigned)((16 * t2 + vRow) * 128
                                                    + 32 * u + vCol));
                    ldsm4t(vF, smb + vcur + off);
                    mma16816(acc[2 * u],     wf[uu], vF);
                    mma16816(acc[2 * u + 1], wf[uu], vF + 2);
                }
            }
        }
    }

    // ---- epilogue: mask, l2norm, + conv3 from fp16 vm ----
    const int quad = lane >> 2;
    const int qi = lane & 3;
    const int r1 = row0 + 16 * wid + quad;
    const int r2 = r1 + 8;
    const float mq1 = mask[b * SS + r1];
    const float mq2 = mask[b * SS + r2];

    float ss1 = 0.0f;
    float ss2 = 0.0f;
    #pragma unroll
    for (int j = 0; j < 8; ++j) {
        ss1 = fmaf(acc[j][0], acc[j][0], ss1);
        ss1 = fmaf(acc[j][1], acc[j][1], ss1);
        ss2 = fmaf(acc[j][2], acc[j][2], ss2);
        ss2 = fmaf(acc[j][3], acc[j][3], ss2);
    }
    ss1 += __shfl_xor_sync(0xffffffff, ss1, 1);
    ss1 += __shfl_xor_sync(0xffffffff, ss1, 2);
    ss2 += __shfl_xor_sync(0xffffffff, ss2, 1);
    ss2 += __shfl_xor_sync(0xffffffff, ss2, 2);
    const float s1 = mq1 / fmaxf(mq1 * sqrtf(ss1), 1e-12f);
    const float s2 = mq2 / fmaxf(mq2 * sqrtf(ss2), 1e-12f);

    const float w0 = convw[h * 3 + 0];
    const float w1 = convw[h * 3 + 1];
    const float w2 = convw[h * 3 + 2];

    #pragma unroll
    for (int j = 0; j < 8; ++j) {
        const int col = 8 * j + qi * 2;
        {
            const __half2* vp = (const __half2*)(g_vf + base
                                                 + (size_t)r1 * DD + col);
            float2 c1 = __half22float2(vp[0]);
            float2 c0;
            c0.x = 0.0f;
            c0.y = 0.0f;
            if (r1 > 0) {
                c0 = __half22float2(vp[-32]);
            }
            float2 c2 = __half22float2(vp[32]);     // r1 <= 2039, safe
            float2 o;
            o.x = fmaf(acc[j][0], s1, w0 * c0.x + w1 * c1.x + w2 * c2.x);
            o.y = fmaf(acc[j][1], s1, w0 * c0.y + w1 * c1.y + w2 * c2.y);
            *(float2*)(out + base + (size_t)r1 * DD + col) = o;
        }
        {
            const __half2* vp = (const __half2*)(g_vf + base
                                                 + (size_t)r2 * DD + col);
            float2 c1 = __half22float2(vp[0]);
            float2 c0 = __half22float2(vp[-32]);    // r2 >= 8, safe
            float2 c2;
            c2.x = 0.0f;
            c2.y = 0.0f;
            if (r2 < SS - 1) {
                c2 = __half22float2(vp[32]);
            }
            float2 o;
            o.x = fmaf(acc[j][2], s2, w0 * c0.x + w1 * c1.x + w2 * c2.x);
            o.y = fmaf(acc[j][3], s2, w0 * c0.y + w1 * c1.y + w2 * c2.y);
            *(float2*)(out + base + (size_t)r2 * DD + col) = o;
        }
    }
}

// ---------------------------------------------------------------------------
extern "C" void kernel_launch(void* const* d_in, const int* in_sizes, int n_in,
                              void* d_out, int out_size)
{
    const float* Q     = (const float*)d_in[0];
    const float* K     = (const float*)d_in[1];
    const float* V     = (const float*)d_in[2];
    const float* mask  = (const float*)d_in[3];
    const float* convw = (const float*)d_in[4];
    float* out = (float*)d_out;

    yoso_prep<<<NROWS / 8, dim3(32, 8)>>>(Q, K, V, mask);

    cudaFuncSetAttribute(yoso_mma, cudaFuncAttributeMaxDynamicSharedMemorySize,
                         SMEM_BYTES);
    dim3 grid(SS / 64, BH);
    yoso_mma<<<grid, 128, SMEM_BYTES>>>(mask, convw, out);
}

// round 15
// speedup vs baseline: 1.0754x; 1.0754x over previous
#include <cuda_runtime.h>
#include <cuda_bf16.h>
#include <cuda_fp16.h>

#define BB 2
#define HH 12
#define SS 2048
#define DD 64
#define BH 24
#define NROWS 49152

// Scratch: fp16 normalized Q/K and masked V
__device__ __half g_qf[(size_t)NROWS * DD];
__device__ __half g_kf[(size_t)NROWS * DD];
__device__ __half g_vf[(size_t)NROWS * DD];

// ---------------------------------------------------------------------------
// helpers
// ---------------------------------------------------------------------------
__device__ __forceinline__ unsigned smem_u32(const void* p)
{
    unsigned a;
    asm("{ .reg .u64 t; cvta.to.shared.u64 t, %1; cvt.u32.u64 %0, t; }"
        : "=r"(a) : "l"(p));
    return a;
}
__device__ __forceinline__ unsigned sw128(unsigned off)
{
    return off ^ ((off >> 3) & 0x70);
}
__device__ __forceinline__ unsigned pack_h2(float lo, float hi)
{
    unsigned r;
    asm("cvt.rn.f16x2.f32 %0, %1, %2;" : "=r"(r) : "f"(hi), "f"(lo));
    return r;
}
__device__ __forceinline__ void ldsm4(unsigned* r, unsigned addr)
{
    asm volatile("ldmatrix.sync.aligned.m8n8.x4.shared.b16 {%0,%1,%2,%3}, [%4];"
                 : "=r"(r[0]), "=r"(r[1]), "=r"(r[2]), "=r"(r[3]) : "r"(addr));
}
__device__ __forceinline__ void ldsm4t(unsigned* r, unsigned addr)
{
    asm volatile("ldmatrix.sync.aligned.m8n8.x4.trans.shared.b16 {%0,%1,%2,%3}, [%4];"
                 : "=r"(r[0]), "=r"(r[1]), "=r"(r[2]), "=r"(r[3]) : "r"(addr));
}
__device__ __forceinline__ void mma16816(float* c, const unsigned* a,
                                         const unsigned* b)
{
    asm volatile(
        "mma.sync.aligned.m16n8k16.row.col.f32.f16.f16.f32 "
        "{%0,%1,%2,%3}, {%4,%5,%6,%7}, {%8,%9}, {%0,%1,%2,%3};"
        : "+f"(c[0]), "+f"(c[1]), "+f"(c[2]), "+f"(c[3])
        : "r"(a[0]), "r"(a[1]), "r"(a[2]), "r"(a[3]), "r"(b[0]), "r"(b[1]));
}
__device__ __forceinline__ void cp16(unsigned dst, const void* src)
{
    asm volatile("cp.async.cg.shared.global [%0], [%1], 16;"
                 :: "r"(dst), "l"(src) : "memory");
}
__device__ __forceinline__ void cp_commit()
{
    asm volatile("cp.async.commit_group;" ::: "memory");
}
template <int N>
__device__ __forceinline__ void cp_wait()
{
    asm volatile("cp.async.wait_group %0;" :: "n"(N) : "memory");
}

// ---------------------------------------------------------------------------
// Prep: l2norm Q,K rows -> fp16; vm = V*mask -> fp16
// ---------------------------------------------------------------------------
__global__ void __launch_bounds__(256) yoso_prep(
    const float* __restrict__ Q, const float* __restrict__ K,
    const float* __restrict__ V, const float* __restrict__ mask)
{
    int r = blockIdx.x * 8 + threadIdx.y;
    int lane = threadIdx.x;
    int s = r % SS;
    int b = r / (HH * SS);
    float m = mask[b * SS + s];
    size_t off = (size_t)r * DD;
    size_t uoff = (size_t)r * 32 + lane;

    {
        float2 v = *(const float2*)(Q + off + lane * 2);
        float sq = v.x * v.x + v.y * v.y;
        sq += __shfl_xor_sync(0xffffffff, sq, 16);
        sq += __shfl_xor_sync(0xffffffff, sq, 8);
        sq += __shfl_xor_sync(0xffffffff, sq, 4);
        sq += __shfl_xor_sync(0xffffffff, sq, 2);
        sq += __shfl_xor_sync(0xffffffff, sq, 1);
        float inv = 1.0f / fmaxf(sqrtf(sq), 1e-12f);
        ((unsigned*)g_qf)[uoff] = pack_h2(v.x * inv, v.y * inv);
    }
    {
        float2 v = *(const float2*)(K + off + lane * 2);
        float sq = v.x * v.x + v.y * v.y;
        sq += __shfl_xor_sync(0xffffffff, sq, 16);
        sq += __shfl_xor_sync(0xffffffff, sq, 8);
        sq += __shfl_xor_sync(0xffffffff, sq, 4);
        sq += __shfl_xor_sync(0xffffffff, sq, 2);
        sq += __shfl_xor_sync(0xffffffff, sq, 1);
        float inv = 1.0f / fmaxf(sqrtf(sq), 1e-12f);
        ((unsigned*)g_kf)[uoff] = pack_h2(v.x * inv, v.y * inv);
    }
    {
        float2 v = *(const float2*)(V + off + lane * 2);
        ((unsigned*)g_vf)[uoff] = pack_h2(v.x * m, v.y * m);
    }
}

// ---------------------------------------------------------------------------
// Fast branchless W(x) = (1 - acos(x)/pi)^8
// ---------------------------------------------------------------------------
__device__ __forceinline__ float yoso_w(float x)
{
    float ax = fminf(fabsf(x), 1.0f);
    float s;
    asm("sqrt.approx.f32 %0, %1;" : "=f"(s) : "f"(1.0f - ax));
    float p = fmaf(-0.00596158f, ax, 0.02363848f);
    p = fmaf(p, ax, -0.06751817f);
    p = fmaf(p, ax, 0.49997907f);
    float u = s * p;
    float t = 0.5f + copysignf(0.5f - u, x);
    float t2 = t * t;
    float t4 = t2 * t2;
    return t4 * t4;
}

// ---------------------------------------------------------------------------
// Main kernel: single-product fp16 mma.sync, double-buffered cp.async
// (one wait + one barrier per key tile). Q A-fragments hoisted once.
// Key-half interleaving for cross-phase ILP; 4 CTAs/SM (full reg budget).
// smem: Q | K0 | K1 | V0 | V1   (8KB each, 40KB total)
// ---------------------------------------------------------------------------
#define SM_Q  0
#define SM_K0 8192
#define SM_K1 16384
#define SM_V0 24576
#define SM_V1 32768
#define SMEM_BYTES 40960

// async-copy one 64x64 fp16 tile (128B rows, SW128 swizzle)
__device__ __forceinline__ void cp_tile64(
    unsigned dst, const __half* g, int tid)
{
    #pragma unroll
    for (int i = 0; i < 4; ++i) {
        int c = tid + i * 128;
        int row = c >> 3;
        int col = c & 7;
        cp16(dst + sw128((unsigned)(row * 128 + col * 16)),
             g + (size_t)row * DD + col * 8);
    }
}

__global__ void __launch_bounds__(128, 4) yoso_mma(
    const float* __restrict__ mask, const float* __restrict__ convw,
    float* __restrict__ out)
{
    extern __shared__ char smc[];
    const int tid = threadIdx.x;
    const int wid = tid >> 5;
    const int lane = tid & 31;
    const int bh = blockIdx.y;
    const int h = bh % HH;
    const int b = bh / HH;
    const int row0 = blockIdx.x * 64;
    const size_t base = (size_t)bh * SS * DD;
    const unsigned smb = smem_u32(smc);

    // prologue: async-load Q, K(0), V(0)
    cp_tile64(smb + SM_Q, g_qf + base + (size_t)row0 * DD, tid);
    cp_tile64(smb + SM_K0, g_kf + base, tid);
    cp_tile64(smb + SM_V0, g_vf + base, tid);
    cp_commit();

    // ldmatrix lane offsets
    const int mm = lane >> 3;
    const int r8 = lane & 7;
    const unsigned aOff = (unsigned)((16 * wid + (mm & 1) * 8 + r8) * 128
                                     + 16 * (mm >> 1));
    const int kRow = r8 + 8 * (mm >> 1);
    const int kCol = 16 * (mm & 1);
    const int vRow = r8 + 8 * (mm & 1);
    const int vCol = 16 * (mm >> 1);

    // Q A-fragments: load ONCE, reuse across all key tiles
    cp_wait<0>();
    __syncthreads();
    unsigned aF[4][4];
    #pragma unroll
    for (int t = 0; t < 4; ++t) {
        ldsm4(aF[t], smb + SM_Q + sw128(aOff + 32 * t));
    }

    float acc[8][4];
    #pragma unroll
    for (int j = 0; j < 8; ++j) {
        #pragma unroll
        for (int i = 0; i < 4; ++i) {
            acc[j][i] = 0.0f;
        }
    }

    for (int kt = 0; kt < SS / 64; ++kt) {
        const unsigned kcur = (kt & 1) ? SM_K1 : SM_K0;
        const unsigned knxt = (kt & 1) ? SM_K0 : SM_K1;
        const unsigned vcur = (kt & 1) ? SM_V1 : SM_V0;
        const unsigned vnxt = (kt & 1) ? SM_V0 : SM_V1;

        // K(kt), V(kt) complete; barrier retires readers of buffers we
        // overwrite next.
        cp_wait<0>();
        __syncthreads();

        // issue K(kt+1), V(kt+1) into the opposite stage
        {
            const int kb2 = ((kt + 1) & 31) * 64;
            cp_tile64(smb + knxt, g_kf + base + (size_t)kb2 * DD, tid);
            cp_tile64(smb + vnxt, g_vf + base + (size_t)kb2 * DD, tid);
            cp_commit();
        }

        // ---- per 32-key half: GEMM1 -> transform -> GEMM2 ----
        #pragma unroll
        for (int hf = 0; hf < 2; ++hf) {
            // GEMM1: dots for keys [32*hf, 32*hf+32)
            float dts[4][4];
            #pragma unroll
            for (int j = 0; j < 4; ++j) {
                #pragma unroll
                for (int i = 0; i < 4; ++i) {
                    dts[j][i] = 0.0f;
                }
            }
            #pragma unroll
            for (int t = 0; t < 4; ++t) {
                #pragma unroll
                for (int uu = 0; uu < 2; ++uu) {
                    int u = 2 * hf + uu;
                    unsigned bF[4];
                    unsigned off = sw128((unsigned)((16 * u + kRow) * 128
                                                    + 32 * t + kCol));
                    ldsm4(bF, smb + kcur + off);
                    mma16816(dts[2 * uu],     aF[t], bF);
                    mma16816(dts[2 * uu + 1], aF[t], bF + 2);
                }
            }

            // transform -> fp16 A-fragments for this half (wf: 8 regs)
            unsigned wf[2][4];
            #pragma unroll
            for (int uu = 0; uu < 2; ++uu) {
                #pragma unroll
                for (int q2 = 0; q2 < 4; ++q2) {
                    int j = 2 * uu + (q2 >> 1);
                    int g = q2 & 1;
                    float f0 = yoso_w(dts[j][2 * g]);
                    float f1 = yoso_w(dts[j][2 * g + 1]);
                    wf[uu][q2] = pack_h2(f0, f1);
                }
            }

            // GEMM2: acc += W[:, keys of this half] * V[keys of this half, :]
            #pragma unroll
            for (int uu = 0; uu < 2; ++uu) {
                int t2 = 2 * hf + uu;
                #pragma unroll
                for (int u = 0; u < 4; ++u) {
                    unsigned vF[4];
                    unsigned off = sw128((unsigned)((16 * t2 + vRow) * 128
                                                    + 32 * u + vCol));
                    ldsm4t(vF, smb + vcur + off);
                    mma16816(acc[2 * u],     wf[uu], vF);
                    mma16816(acc[2 * u + 1], wf[uu], vF + 2);
                }
            }
        }
    }

    // ---- epilogue: mask, l2norm, + conv3 from fp16 vm ----
    const int quad = lane >> 2;
    const int qi = lane & 3;
    const int r1 = row0 + 16 * wid + quad;
    const int r2 = r1 + 8;
    const float mq1 = mask[b * SS + r1];
    const float mq2 = mask[b * SS + r2];

    float ss1 = 0.0f;
    float ss2 = 0.0f;
    #pragma unroll
    for (int j = 0; j < 8; ++j) {
        ss1 = fmaf(acc[j][0], acc[j][0], ss1);
        ss1 = fmaf(acc[j][1], acc[j][1], ss1);
        ss2 = fmaf(acc[j][2], acc[j][2], ss2);
        ss2 = fmaf(acc[j][3], acc[j][3], ss2);
    }
    ss1 += __shfl_xor_sync(0xffffffff, ss1, 1);
    ss1 += __shfl_xor_sync(0xffffffff, ss1, 2);
    ss2 += __shfl_xor_sync(0xffffffff, ss2, 1);
    ss2 += __shfl_xor_sync(0xffffffff, ss2, 2);
    const float s1 = mq1 / fmaxf(mq1 * sqrtf(ss1), 1e-12f);
    const float s2 = mq2 / fmaxf(mq2 * sqrtf(ss2), 1e-12f);

    const float w0 = convw[h * 3 + 0];
    const float w1 = convw[h * 3 + 1];
    const float w2 = convw[h * 3 + 2];

    #pragma unroll
    for (int j = 0; j < 8; ++j) {
        const int col = 8 * j + qi * 2;
        {
            const __half2* vp = (const __half2*)(g_vf + base
                                                 + (size_t)r1 * DD + col);
            float2 c1 = __half22float2(vp[0]);
            float2 c0;
            c0.x = 0.0f;
            c0.y = 0.0f;
            if (r1 > 0) {
                c0 = __half22float2(vp[-32]);
            }
            float2 c2 = __half22float2(vp[32]);     // r1 <= 2039, safe
            float2 o;
            o.x = fmaf(acc[j][0], s1, w0 * c0.x + w1 * c1.x + w2 * c2.x);
            o.y = fmaf(acc[j][1], s1, w0 * c0.y + w1 * c1.y + w2 * c2.y);
            *(float2*)(out + base + (size_t)r1 * DD + col) = o;
        }
        {
            const __half2* vp = (const __half2*)(g_vf + base
                                                 + (size_t)r2 * DD + col);
            float2 c1 = __half22float2(vp[0]);
            float2 c0 = __half22float2(vp[-32]);    // r2 >= 8, safe
            float2 c2;
            c2.x = 0.0f;
            c2.y = 0.0f;
            if (r2 < SS - 1) {
                c2 = __half22float2(vp[32]);
            }
            float2 o;
            o.x = fmaf(acc[j][2], s2, w0 * c0.x + w1 * c1.x + w2 * c2.x);
            o.y = fmaf(acc[j][3], s2, w0 * c0.y + w1 * c1.y + w2 * c2.y);
            *(float2*)(out + base + (size_t)r2 * DD + col) = o;
        }
    }
}

// ---------------------------------------------------------------------------
extern "C" void kernel_launch(void* const* d_in, const int* in_sizes, int n_in,
                              void* d_out, int out_size)
{
    const float* Q     = (const float*)d_in[0];
    const float* K     = (const float*)d_in[1];
    const float* V     = (const float*)d_in[2];
    const float* mask  = (const float*)d_in[3];
    const float* convw = (const float*)d_in[4];
    float* out = (float*)d_out;

    yoso_prep<<<NROWS / 8, dim3(32, 8)>>>(Q, K, V, mask);

    cudaFuncSetAttribute(yoso_mma, cudaFuncAttributeMaxDynamicSharedMemorySize,
                         SMEM_BYTES);
    dim3 grid(SS / 64, BH);
    yoso_mma<<<grid, 128, SMEM_BYTES>>>(mask, convw, out);
}

// round 16
// speedup vs baseline: 1.1294x; 1.0502x over previous
#include <cuda_runtime.h>
#include <cuda_bf16.h>
#include <cuda_fp16.h>

#define BB 2
#define HH 12
#define SS 2048
#define DD 64
#define BH 24
#define NROWS 49152

// Scratch: fp16 normalized Q/K and masked V
__device__ __half g_qf[(size_t)NROWS * DD];
__device__ __half g_kf[(size_t)NROWS * DD];
__device__ __half g_vf[(size_t)NROWS * DD];

typedef unsigned long long ull;

// ---------------------------------------------------------------------------
// helpers
// ---------------------------------------------------------------------------
__device__ __forceinline__ unsigned smem_u32(const void* p)
{
    unsigned a;
    asm("{ .reg .u64 t; cvta.to.shared.u64 t, %1; cvt.u32.u64 %0, t; }"
        : "=r"(a) : "l"(p));
    return a;
}
__device__ __forceinline__ unsigned sw128(unsigned off)
{
    return off ^ ((off >> 3) & 0x70);
}
__device__ __forceinline__ unsigned pack_h2(float lo, float hi)
{
    unsigned r;
    asm("cvt.rn.f16x2.f32 %0, %1, %2;" : "=r"(r) : "f"(hi), "f"(lo));
    return r;
}
__device__ __forceinline__ ull pk2(float lo, float hi)
{
    ull r;
    asm("mov.b64 %0, {%1, %2};" : "=l"(r) : "f"(lo), "f"(hi));
    return r;
}
__device__ __forceinline__ void upk2(ull v, float& lo, float& hi)
{
    asm("mov.b64 {%0, %1}, %2;" : "=f"(lo), "=f"(hi) : "l"(v));
}
__device__ __forceinline__ ull fma2_(ull a, ull b, ull c)
{
    ull d;
    asm("fma.rn.f32x2 %0, %1, %2, %3;" : "=l"(d) : "l"(a), "l"(b), "l"(c));
    return d;
}
__device__ __forceinline__ ull mul2_(ull a, ull b)
{
    ull d;
    asm("mul.rn.f32x2 %0, %1, %2;" : "=l"(d) : "l"(a), "l"(b));
    return d;
}
__device__ __forceinline__ ull add2_(ull a, ull b)
{
    ull d;
    asm("add.rn.f32x2 %0, %1, %2;" : "=l"(d) : "l"(a), "l"(b));
    return d;
}
__device__ __forceinline__ void ldsm4(unsigned* r, unsigned addr)
{
    asm volatile("ldmatrix.sync.aligned.m8n8.x4.shared.b16 {%0,%1,%2,%3}, [%4];"
                 : "=r"(r[0]), "=r"(r[1]), "=r"(r[2]), "=r"(r[3]) : "r"(addr));
}
__device__ __forceinline__ void ldsm4t(unsigned* r, unsigned addr)
{
    asm volatile("ldmatrix.sync.aligned.m8n8.x4.trans.shared.b16 {%0,%1,%2,%3}, [%4];"
                 : "=r"(r[0]), "=r"(r[1]), "=r"(r[2]), "=r"(r[3]) : "r"(addr));
}
__device__ __forceinline__ void mma16816(float* c, const unsigned* a,
                                         const unsigned* b)
{
    asm volatile(
        "mma.sync.aligned.m16n8k16.row.col.f32.f16.f16.f32 "
        "{%0,%1,%2,%3}, {%4,%5,%6,%7}, {%8,%9}, {%0,%1,%2,%3};"
        : "+f"(c[0]), "+f"(c[1]), "+f"(c[2]), "+f"(c[3])
        : "r"(a[0]), "r"(a[1]), "r"(a[2]), "r"(a[3]), "r"(b[0]), "r"(b[1]));
}
__device__ __forceinline__ void cp16(unsigned dst, const void* src)
{
    asm volatile("cp.async.cg.shared.global [%0], [%1], 16;"
                 :: "r"(dst), "l"(src) : "memory");
}
__device__ __forceinline__ void cp_commit()
{
    asm volatile("cp.async.commit_group;" ::: "memory");
}
template <int N>
__device__ __forceinline__ void cp_wait()
{
    asm volatile("cp.async.wait_group %0;" :: "n"(N) : "memory");
}

// ---------------------------------------------------------------------------
// Prep: l2norm Q,K rows -> fp16; vm = V*mask -> fp16
// ---------------------------------------------------------------------------
__global__ void __launch_bounds__(256) yoso_prep(
    const float* __restrict__ Q, const float* __restrict__ K,
    const float* __restrict__ V, const float* __restrict__ mask)
{
    int r = blockIdx.x * 8 + threadIdx.y;
    int lane = threadIdx.x;
    int s = r % SS;
    int b = r / (HH * SS);
    float m = mask[b * SS + s];
    size_t off = (size_t)r * DD;
    size_t uoff = (size_t)r * 32 + lane;

    {
        float2 v = *(const float2*)(Q + off + lane * 2);
        float sq = v.x * v.x + v.y * v.y;
        sq += __shfl_xor_sync(0xffffffff, sq, 16);
        sq += __shfl_xor_sync(0xffffffff, sq, 8);
        sq += __shfl_xor_sync(0xffffffff, sq, 4);
        sq += __shfl_xor_sync(0xffffffff, sq, 2);
        sq += __shfl_xor_sync(0xffffffff, sq, 1);
        float inv = 1.0f / fmaxf(sqrtf(sq), 1e-12f);
        ((unsigned*)g_qf)[uoff] = pack_h2(v.x * inv, v.y * inv);
    }
    {
        float2 v = *(const float2*)(K + off + lane * 2);
        float sq = v.x * v.x + v.y * v.y;
        sq += __shfl_xor_sync(0xffffffff, sq, 16);
        sq += __shfl_xor_sync(0xffffffff, sq, 8);
        sq += __shfl_xor_sync(0xffffffff, sq, 4);
        sq += __shfl_xor_sync(0xffffffff, sq, 2);
        sq += __shfl_xor_sync(0xffffffff, sq, 1);
        float inv = 1.0f / fmaxf(sqrtf(sq), 1e-12f);
        ((unsigned*)g_kf)[uoff] = pack_h2(v.x * inv, v.y * inv);
    }
    {
        float2 v = *(const float2*)(V + off + lane * 2);
        ((unsigned*)g_vf)[uoff] = pack_h2(v.x * m, v.y * m);
    }
}

// ---------------------------------------------------------------------------
// Packed-pair W(x) = (1 - acos(x)/pi)^8 for two dots -> one f16x2.
// Negated poly so (0.5 - u) is a single packed add; copysign per half;
// all fp32 arithmetic identical to the scalar version.
// ---------------------------------------------------------------------------
__device__ __forceinline__ unsigned yoso_w2(float x0, float x1)
{
    float ax0 = fminf(fabsf(x0), 1.0f);
    float ax1 = fminf(fabsf(x1), 1.0f);
    float s0, s1;
    asm("sqrt.approx.f32 %0, %1;" : "=f"(s0) : "f"(1.0f - ax0));
    asm("sqrt.approx.f32 %0, %1;" : "=f"(s1) : "f"(1.0f - ax1));
    ull axp = pk2(ax0, ax1);
    ull sp  = pk2(s0, s1);
    // -p(ax): negated A&S 4.4.45 with 1/pi folded in
    ull p = fma2_(pk2(0.00596158f, 0.00596158f), axp,
                  pk2(-0.02363848f, -0.02363848f));
    p = fma2_(p, axp, pk2(0.06751817f, 0.06751817f));
    p = fma2_(p, axp, pk2(-0.49997907f, -0.49997907f));
    ull u = mul2_(sp, p);                    // -acos(|x|)/pi
    ull w = add2_(u, pk2(0.5f, 0.5f));       // 0.5 - acos(|x|)/pi  (>= 0)
    float w0, w1;
    upk2(w, w0, w1);
    w0 = copysignf(w0, x0);
    w1 = copysignf(w1, x1);
    ull t = add2_(pk2(w0, w1), pk2(0.5f, 0.5f));
    ull t2 = mul2_(t, t);
    ull t4 = mul2_(t2, t2);
    ull t8 = mul2_(t4, t4);
    float f0, f1;
    upk2(t8, f0, f1);
    return pack_h2(f0, f1);
}

// ---------------------------------------------------------------------------
// Main kernel: single-product fp16 mma.sync, double-buffered cp.async
// (one wait + one barrier per key tile). Q A-fragments hoisted once.
// Key-half interleaving; packed f32x2 transform; 4 CTAs/SM.
// smem: Q | K0 | K1 | V0 | V1   (8KB each, 40KB total)
// ---------------------------------------------------------------------------
#define SM_Q  0
#define SM_K0 8192
#define SM_K1 16384
#define SM_V0 24576
#define SM_V1 32768
#define SMEM_BYTES 40960

// async-copy one 64x64 fp16 tile (128B rows, SW128 swizzle)
__device__ __forceinline__ void cp_tile64(
    unsigned dst, const __half* g, int tid)
{
    #pragma unroll
    for (int i = 0; i < 4; ++i) {
        int c = tid + i * 128;
        int row = c >> 3;
        int col = c & 7;
        cp16(dst + sw128((unsigned)(row * 128 + col * 16)),
             g + (size_t)row * DD + col * 8);
    }
}

__global__ void __launch_bounds__(128, 4) yoso_mma(
    const float* __restrict__ mask, const float* __restrict__ convw,
    float* __restrict__ out)
{
    extern __shared__ char smc[];
    const int tid = threadIdx.x;
    const int wid = tid >> 5;
    const int lane = tid & 31;
    const int bh = blockIdx.y;
    const int h = bh % HH;
    const int b = bh / HH;
    const int row0 = blockIdx.x * 64;
    const size_t base = (size_t)bh * SS * DD;
    const unsigned smb = smem_u32(smc);

    // prologue: async-load Q, K(0), V(0)
    cp_tile64(smb + SM_Q, g_qf + base + (size_t)row0 * DD, tid);
    cp_tile64(smb + SM_K0, g_kf + base, tid);
    cp_tile64(smb + SM_V0, g_vf + base, tid);
    cp_commit();

    // ldmatrix lane offsets
    const int mm = lane >> 3;
    const int r8 = lane & 7;
    const unsigned aOff = (unsigned)((16 * wid + (mm & 1) * 8 + r8) * 128
                                     + 16 * (mm >> 1));
    const int kRow = r8 + 8 * (mm >> 1);
    const int kCol = 16 * (mm & 1);
    const int vRow = r8 + 8 * (mm & 1);
    const int vCol = 16 * (mm >> 1);

    // Q A-fragments: load ONCE, reuse across all key tiles
    cp_wait<0>();
    __syncthreads();
    unsigned aF[4][4];
    #pragma unroll
    for (int t = 0; t < 4; ++t) {
        ldsm4(aF[t], smb + SM_Q + sw128(aOff + 32 * t));
    }

    float acc[8][4];
    #pragma unroll
    for (int j = 0; j < 8; ++j) {
        #pragma unroll
        for (int i = 0; i < 4; ++i) {
            acc[j][i] = 0.0f;
        }
    }

    for (int kt = 0; kt < SS / 64; ++kt) {
        const unsigned kcur = (kt & 1) ? SM_K1 : SM_K0;
        const unsigned knxt = (kt & 1) ? SM_K0 : SM_K1;
        const unsigned vcur = (kt & 1) ? SM_V1 : SM_V0;
        const unsigned vnxt = (kt & 1) ? SM_V0 : SM_V1;

        // K(kt), V(kt) complete; barrier retires readers of buffers we
        // overwrite next.
        cp_wait<0>();
        __syncthreads();

        // issue K(kt+1), V(kt+1) into the opposite stage
        {
            const int kb2 = ((kt + 1) & 31) * 64;
            cp_tile64(smb + knxt, g_kf + base + (size_t)kb2 * DD, tid);
            cp_tile64(smb + vnxt, g_vf + base + (size_t)kb2 * DD, tid);
            cp_commit();
        }

        // ---- per 32-key half: GEMM1 -> transform -> GEMM2 ----
        #pragma unroll
        for (int hf = 0; hf < 2; ++hf) {
            // GEMM1: dots for keys [32*hf, 32*hf+32)
            float dts[4][4];
            #pragma unroll
            for (int j = 0; j < 4; ++j) {
                #pragma unroll
                for (int i = 0; i < 4; ++i) {
                    dts[j][i] = 0.0f;
                }
            }
            #pragma unroll
            for (int t = 0; t < 4; ++t) {
                #pragma unroll
                for (int uu = 0; uu < 2; ++uu) {
                    int u = 2 * hf + uu;
                    unsigned bF[4];
                    unsigned off = sw128((unsigned)((16 * u + kRow) * 128
                                                    + 32 * t + kCol));
                    ldsm4(bF, smb + kcur + off);
                    mma16816(dts[2 * uu],     aF[t], bF);
                    mma16816(dts[2 * uu + 1], aF[t], bF + 2);
                }
            }

            // transform -> fp16 A-fragments (packed f32x2 pairs)
            unsigned wf[2][4];
            #pragma unroll
            for (int uu = 0; uu < 2; ++uu) {
                #pragma unroll
                for (int q2 = 0; q2 < 4; ++q2) {
                    int j = 2 * uu + (q2 >> 1);
                    int g = q2 & 1;
                    wf[uu][q2] = yoso_w2(dts[j][2 * g], dts[j][2 * g + 1]);
                }
            }

            // GEMM2: acc += W[:, keys of this half] * V[keys of this half, :]
            #pragma unroll
            for (int uu = 0; uu < 2; ++uu) {
                int t2 = 2 * hf + uu;
                #pragma unroll
                for (int u = 0; u < 4; ++u) {
                    unsigned vF[4];
                    unsigned off = sw128((unsigned)((16 * t2 + vRow) * 128
                                                    + 32 * u + vCol));
                    ldsm4t(vF, smb + vcur + off);
                    mma16816(acc[2 * u],     wf[uu], vF);
                    mma16816(acc[2 * u + 1], wf[uu], vF + 2);
                }
            }
        }
    }

    // ---- epilogue: mask, l2norm, + conv3 from fp16 vm ----
    const int quad = lane >> 2;
    const int qi = lane & 3;
    const int r1 = row0 + 16 * wid + quad;
    const int r2 = r1 + 8;
    const float mq1 = mask[b * SS + r1];
    const float mq2 = mask[b * SS + r2];

    float ss1 = 0.0f;
    float ss2 = 0.0f;
    #pragma unroll
    for (int j = 0; j < 8; ++j) {
        ss1 = fmaf(acc[j][0], acc[j][0], ss1);
        ss1 = fmaf(acc[j][1], acc[j][1], ss1);
        ss2 = fmaf(acc[j][2], acc[j][2], ss2);
        ss2 = fmaf(acc[j][3], acc[j][3], ss2);
    }
    ss1 += __shfl_xor_sync(0xffffffff, ss1, 1);
    ss1 += __shfl_xor_sync(0xffffffff, ss1, 2);
    ss2 += __shfl_xor_sync(0xffffffff, ss2, 1);
    ss2 += __shfl_xor_sync(0xffffffff, ss2, 2);
    const float s1 = mq1 / fmaxf(mq1 * sqrtf(ss1), 1e-12f);
    const float s2 = mq2 / fmaxf(mq2 * sqrtf(ss2), 1e-12f);

    const float w0 = convw[h * 3 + 0];
    const float w1 = convw[h * 3 + 1];
    const float w2 = convw[h * 3 + 2];

    #pragma unroll
    for (int j = 0; j < 8; ++j) {
        const int col = 8 * j + qi * 2;
        {
            const __half2* vp = (const __half2*)(g_vf + base
                                                 + (size_t)r1 * DD + col);
            float2 c1 = __half22float2(vp[0]);
            float2 c0;
            c0.x = 0.0f;
            c0.y = 0.0f;
            if (r1 > 0) {
                c0 = __half22float2(vp[-32]);
            }
            float2 c2 = __half22float2(vp[32]);     // r1 <= 2039, safe
            float2 o;
            o.x = fmaf(acc[j][0], s1, w0 * c0.x + w1 * c1.x + w2 * c2.x);
            o.y = fmaf(acc[j][1], s1, w0 * c0.y + w1 * c1.y + w2 * c2.y);
            *(float2*)(out + base + (size_t)r1 * DD + col) = o;
        }
        {
            const __half2* vp = (const __half2*)(g_vf + base
                                                 + (size_t)r2 * DD + col);
            float2 c1 = __half22float2(vp[0]);
            float2 c0 = __half22float2(vp[-32]);    // r2 >= 8, safe
            float2 c2;
            c2.x = 0.0f;
            c2.y = 0.0f;
            if (r2 < SS - 1) {
                c2 = __half22float2(vp[32]);
            }
            float2 o;
            o.x = fmaf(acc[j][2], s2, w0 * c0.x + w1 * c1.x + w2 * c2.x);
            o.y = fmaf(acc[j][3], s2, w0 * c0.y + w1 * c1.y + w2 * c2.y);
            *(float2*)(out + base + (size_t)r2 * DD + col) = o;
        }
    }
}

// ---------------------------------------------------------------------------
extern "C" void kernel_launch(void* const* d_in, const int* in_sizes, int n_in,
                              void* d_out, int out_size)
{
    const float* Q     = (const float*)d_in[0];
    const float* K     = (const float*)d_in[1];
    const float* V     = (const float*)d_in[2];
    const float* mask  = (const float*)d_in[3];
    const float* convw = (const float*)d_in[4];
    float* out = (float*)d_out;

    yoso_prep<<<NROWS / 8, dim3(32, 8)>>>(Q, K, V, mask);

    cudaFuncSetAttribute(yoso_mma, cudaFuncAttributeMaxDynamicSharedMemorySize,
                         SMEM_BYTES);
    dim3 grid(SS / 64, BH);
    yoso_mma<<<grid, 128, SMEM_BYTES>>>(mask, convw, out);
}